// round 7
// baseline (speedup 1.0000x reference)
#include <cuda_runtime.h>
#include <cstdint>

#define JAX_PARTITIONABLE 1

#define Bn   32
#define Gn   50
#define Hn   64
#define Wn   64
#define An   9
#define HWn  4096
#define KAn  36864
#define HALFN 9312
#define CAP  18624
#define CAPOV 7168
#define ECAP 512

__constant__ int   c_ixmin[9]={6,11,23,4,8,16,3,5,11};
__constant__ int   c_ixmax[9]={57,52,40,59,55,47,60,58,52};
__constant__ int   c_iymin[9]={3,6,12,4,8,16,5,11,22};
__constant__ int   c_iymax[9]={60,57,51,59,55,47,58,52,41};
__constant__ float c_ax1[9]={-84.f,-176.f,-360.f,-56.f,-120.f,-248.f,-36.f,-80.f,-168.f};
__constant__ float c_ay1[9]={-40.f,-88.f,-184.f,-56.f,-120.f,-248.f,-80.f,-168.f,-344.f};
__constant__ float c_ax2[9]={99.f,191.f,375.f,71.f,135.f,263.f,51.f,95.f,183.f};
__constant__ float c_ay2[9]={55.f,103.f,199.f,71.f,135.f,263.f,95.f,183.f,359.f};
__constant__ float c_aw[9] ={184.f,368.f,736.f,128.f,256.f,512.f,88.f,176.f,352.f};
__constant__ float c_ah[9] ={96.f,192.f,384.f,128.f,256.f,512.f,176.f,352.f,704.f};
__constant__ float c_area[9]={17664.f,70656.f,282624.f,16384.f,65536.f,262144.f,15488.f,61952.f,247808.f};

// scratch — all zero-initialized at module load; k_final re-clears flags/cnt
// at the end of every run so each kernel_launch starts from identical state.
__device__ unsigned       g_keys[Bn][4];
__device__ unsigned       g_flags[Bn*KAn];   // bit0: any ov>=0.7, bit1: any ov>=0.3, bit2: hit
__device__ unsigned char  g_cls[Bn*KAn];     // 0=bg,1=fg,2=ignore,3=outside (rewritten fully each run)
__device__ unsigned       g_v[Bn*KAn];       // 23-bit uniform payload (valid where cls<2)
__device__ unsigned short g_nidx[KAn];       // compact index table (b-independent, recomputed each run)
__device__ int            g_cnt[Bn*2];
__device__ unsigned       g_lv[Bn*2*CAP];
__device__ int            g_ln[Bn*2*CAP];
__device__ unsigned       g_thrV[Bn*2];      // fully rewritten each run
__device__ int            g_thrN[Bn*2];

// ---------------- Threefry-2x32 (bit-exact with jax) ----------------
__device__ __forceinline__ void tf2x32(unsigned k0, unsigned k1, unsigned x0, unsigned x1,
                                       unsigned& o0, unsigned& o1) {
    unsigned k2 = k0 ^ k1 ^ 0x1BD11BDAu;
    x0 += k0; x1 += k1;
#define TFR(r) { x0 += x1; x1 = (x1 << (r)) | (x1 >> (32 - (r))); x1 ^= x0; }
    TFR(13) TFR(15) TFR(26) TFR(6)   x0 += k1; x1 += k2 + 1u;
    TFR(17) TFR(29) TFR(16) TFR(24)  x0 += k2; x1 += k0 + 2u;
    TFR(13) TFR(15) TFR(26) TFR(6)   x0 += k0; x1 += k1 + 3u;
    TFR(17) TFR(29) TFR(16) TFR(24)  x0 += k1; x1 += k2 + 4u;
    TFR(13) TFR(15) TFR(26) TFR(6)   x0 += k2; x1 += k0 + 5u;
#undef TFR
    o0 = x0; o1 = x1;
}

__device__ __forceinline__ unsigned ubits(unsigned k0, unsigned k1, int n) {
#if JAX_PARTITIONABLE
    unsigned y0, y1;
    tf2x32(k0, k1, 0u, (unsigned)n, y0, y1);
    return y0 ^ y1;
#else
    unsigned y0, y1;
    if (n < HALFN) { tf2x32(k0, k1, (unsigned)n, (unsigned)(n + HALFN), y0, y1); return y0; }
    else           { tf2x32(k0, k1, (unsigned)(n - HALFN), (unsigned)n, y0, y1); return y1; }
#endif
}

__device__ __forceinline__ int compact_index(int iy, int ix, int a) {
    int n = 0;
#pragma unroll
    for (int j = 0; j < 9; j++) {
        int cy = min(iy, c_iymax[j] + 1) - c_iymin[j]; cy = max(cy, 0);
        int cx = c_ixmax[j] - c_ixmin[j] + 1;
        n += cy * cx;
        if (iy >= c_iymin[j] && iy <= c_iymax[j]) {
            int px = min(ix, c_ixmax[j] + 1) - c_ixmin[j]; px = max(px, 0);
            n += px;
            if (j < a && ix >= c_ixmin[j] && ix <= c_ixmax[j]) n += 1;
        }
    }
    return n;
}

__device__ __forceinline__ float iou_f(float ax1, float ay1, float ax2, float ay2, float areaa,
                                       float gx1, float gy1, float gx2, float gy2, float areag) {
    float iw = __fadd_rn(__fsub_rn(fminf(ax2, gx2), fmaxf(ax1, gx1)), 1.0f); iw = fmaxf(iw, 0.0f);
    float ih = __fadd_rn(__fsub_rn(fminf(ay2, gy2), fmaxf(ay1, gy1)), 1.0f); ih = fmaxf(ih, 0.0f);
    float inter = __fmul_rn(iw, ih);
    return __fdiv_rn(inter, __fsub_rn(__fadd_rn(areaa, areag), inter));
}

// conservative window bounds for anchor type a vs gt box
__device__ __forceinline__ void win(int a, float gx1, float gy1, float gx2, float gy2,
                                    int& xlo, int& xhi, int& ylo, int& yhi) {
    xlo = max(c_ixmin[a], (int)floorf((gx1 - 1.0f - c_ax2[a]) * 0.0625f));
    xhi = min(c_ixmax[a], (int)ceilf((gx2 + 1.0f - c_ax1[a]) * 0.0625f));
    ylo = max(c_iymin[a], (int)floorf((gy1 - 1.0f - c_ay2[a]) * 0.0625f));
    yhi = min(c_iymax[a], (int)ceilf((gy2 + 1.0f - c_ay1[a]) * 0.0625f));
}

// one block per (b,g): pass A computes windowed IoUs (cached in smem), ORs
// threshold flag bits, and block-reduces this gt's max; pass B scans cached
// IoUs flagging ov==gt_max hits. Blocks <144 additionally build the nidx
// table; block 0 computes the per-image Threefry keys.
__global__ void __launch_bounds__(256) k_gtpass(const float* __restrict__ gt) {
    __shared__ float sov[CAPOV];
    __shared__ float red[256];
    int blk = blockIdx.x;
    int t = threadIdx.x;
    if (blk < KAn / 256) {
        int i = blk * 256 + t;
        int a = i / HWn; int r = i - a * HWn; int iy = r >> 6; int ix = r & 63;
        g_nidx[i] = (unsigned short)compact_index(iy, ix, a);
    }
    if (blk == 0 && t < Bn) {
        unsigned f0, f1, q0, q1, b0, b1;
        tf2x32(0u, 42u, 0u, (unsigned)t, b0, b1);
        tf2x32(b0, b1, 0u, 0u, f0, f1);
        tf2x32(b0, b1, 0u, 1u, q0, q1);
        g_keys[t][0] = f0; g_keys[t][1] = f1; g_keys[t][2] = q0; g_keys[t][3] = q1;
    }
    int b = blk / Gn, g = blk - b * Gn;
    const float* gb = gt + (size_t)(b * Gn + g) * 4;
    float gx1 = gb[0], gy1 = gb[1], gx2 = gb[2], gy2 = gb[3];
    float gw = __fadd_rn(__fsub_rn(gx2, gx1), 1.0f);
    float gh = __fadd_rn(__fsub_rn(gy2, gy1), 1.0f);
    float areag = __fmul_rn(gw, gh);
    float best = 0.0f;

    int xlo9[9], ylo9[9], nx9[9], tot9[9], off9[9];
    int off = 0;
#pragma unroll
    for (int a = 0; a < 9; a++) {
        int xlo, xhi, ylo, yhi;
        win(a, gx1, gy1, gx2, gy2, xlo, xhi, ylo, yhi);
        int nx = xhi - xlo + 1, ny = yhi - ylo + 1;
        int tot = (nx > 0 && ny > 0) ? nx * ny : 0;
        xlo9[a] = xlo; ylo9[a] = ylo; nx9[a] = nx; tot9[a] = tot; off9[a] = off;
        off += tot;
    }
    bool cache = (off <= CAPOV);

#pragma unroll
    for (int a = 0; a < 9; a++) {
        int tot = tot9[a];
        if (tot == 0) continue;
        int xlo = xlo9[a], ylo = ylo9[a], nx = nx9[a], base = off9[a];
        float ax1 = c_ax1[a], ay1 = c_ay1[a], ax2 = c_ax2[a], ay2 = c_ay2[a], areaa = c_area[a];
        for (int q0 = t; q0 < tot; q0 += 256) {
            int q = q0 / nx;
            int iy = ylo + q, ix = xlo + q0 - q * nx;
            float sx = (float)(ix << 4), sy = (float)(iy << 4);
            float ov = iou_f(ax1 + sx, ay1 + sy, ax2 + sx, ay2 + sy, areaa,
                             gx1, gy1, gx2, gy2, areag);
            if (cache) sov[base + q0] = ov;
            best = fmaxf(best, ov);
            unsigned f = (ov >= 0.7f ? 1u : 0u) | (ov >= 0.3f ? 2u : 0u);
            if (f) atomicOr(&g_flags[(size_t)b * KAn + a * HWn + (iy << 6) + ix], f);
        }
    }
    red[t] = best;
    __syncthreads();
    for (int s = 128; s > 0; s >>= 1) {
        if (t < s) red[t] = fmaxf(red[t], red[t + s]);
        __syncthreads();
    }
    float gm = red[0];
    if (gm <= 0.0f) return;
    // pass B: flag anchors achieving this gt's max overlap
#pragma unroll
    for (int a = 0; a < 9; a++) {
        int tot = tot9[a];
        if (tot == 0) continue;
        int xlo = xlo9[a], ylo = ylo9[a], nx = nx9[a], base = off9[a];
        float ax1 = c_ax1[a], ay1 = c_ay1[a], ax2 = c_ax2[a], ay2 = c_ay2[a], areaa = c_area[a];
        for (int q0 = t; q0 < tot; q0 += 256) {
            int q = q0 / nx;
            int iy = ylo + q, ix = xlo + q0 - q * nx;
            float ov;
            if (cache) {
                ov = sov[base + q0];
            } else {
                float sx = (float)(ix << 4), sy = (float)(iy << 4);
                ov = iou_f(ax1 + sx, ay1 + sy, ax2 + sx, ay2 + sy, areaa,
                           gx1, gy1, gx2, gy2, areag);
            }
            if (ov == gm) atomicOr(&g_flags[(size_t)b * KAn + a * HWn + (iy << 6) + ix], 4u);
        }
    }
}

__global__ void __launch_bounds__(256) k_label() {
    __shared__ int lcnt[2];
    __shared__ int lbase[2];
    int b = blockIdx.y;
    int t = threadIdx.x;
    if (t < 2) lcnt[t] = 0;
    __syncthreads();
    int j = blockIdx.x * 256 + t;       // a-major
    int a = j / HWn; int r = j - a * HWn; int iy = r >> 6; int ix = r & 63;
    unsigned char cls = 3;
    int c = 0, lp = 0, n = 0; unsigned v = 0;
    if (!(ix < c_ixmin[a] || ix > c_ixmax[a] || iy < c_iymin[a] || iy > c_iymax[a])) {
        unsigned f = g_flags[(size_t)b * KAn + j];
        cls = (f & 5u) ? (unsigned char)1 : ((f & 2u) ? (unsigned char)2 : (unsigned char)0);
        if (cls < 2) {
            c = cls ? 0 : 1;
            n = g_nidx[j];
            v = ubits(g_keys[b][c * 2], g_keys[b][c * 2 + 1], n) >> 9;
            g_v[(size_t)b * KAn + j] = v;
            lp = atomicAdd(&lcnt[c], 1);
        }
    }
    g_cls[(size_t)b * KAn + j] = cls;
    __syncthreads();
    if (t < 2) lbase[t] = lcnt[t] ? atomicAdd(&g_cnt[b * 2 + t], lcnt[t]) : 0;
    __syncthreads();
    if (cls < 2) {
        int p = (b * 2 + c) * CAP + lbase[c] + lp;
        g_lv[p] = v;
        g_ln[p] = n;
    }
}

__device__ void find_kth(unsigned* hist, int per, unsigned k, unsigned* wsum,
                         int* s_bin, unsigned* s_below, int tid) {
    int base = tid * per;
    unsigned mysum = 0;
    for (int x = 0; x < per; x++) mysum += hist[base + x];
    unsigned lane = tid & 31, wid = tid >> 5;
    unsigned inc = mysum;
#pragma unroll
    for (int off = 1; off < 32; off <<= 1) {
        unsigned nv = __shfl_up_sync(0xffffffffu, inc, off);
        if (lane >= off) inc += nv;
    }
    if (lane == 31) wsum[wid] = inc;
    __syncthreads();
    if (wid == 0) {
        unsigned w = wsum[lane];
        unsigned iw = w;
#pragma unroll
        for (int off = 1; off < 32; off <<= 1) {
            unsigned nv = __shfl_up_sync(0xffffffffu, iw, off);
            if (lane >= off) iw += nv;
        }
        wsum[lane] = iw - w;
    }
    __syncthreads();
    unsigned run = wsum[wid] + (inc - mysum);
    for (int x = 0; x < per; x++) {
        unsigned h = hist[base + x];
        if (run < k && k <= run + h) { *s_bin = base + x; *s_below = run; }
        run += h;
    }
    __syncthreads();
}

__global__ void __launch_bounds__(1024) k_select() {
    __shared__ unsigned hist[4096];
    __shared__ unsigned wsum[32];
    __shared__ int s_bin; __shared__ unsigned s_below;
    __shared__ unsigned s_ev[ECAP]; __shared__ int s_en[ECAP];
    __shared__ int s_cnt; __shared__ unsigned s_V; __shared__ int s_cut;
    int bc = blockIdx.x; int b = bc >> 1; int c = bc & 1;
    int tid = threadIdx.x;
    int nfg = g_cnt[b * 2 + 0], nbg = g_cnt[b * 2 + 1];
    int m = c ? nbg : nfg;
    unsigned k = c ? (unsigned)(256 - min(nfg, 128)) : 128u;
    if ((unsigned)m <= k) {
        if (tid == 0) { g_thrV[bc] = 0xFFFFFFFFu; g_thrN[bc] = 0x7FFFFFFF; }
        return;
    }
    const unsigned* lv = g_lv + (size_t)bc * CAP;
    const int* ln = g_ln + (size_t)bc * CAP;

    // pass 1: 12-bit histogram
    for (int x = tid; x < 4096; x += 1024) hist[x] = 0;
    __syncthreads();
    for (int i = tid; i < m; i += 1024) atomicAdd(&hist[lv[i] >> 11], 1u);
    __syncthreads();
    find_kth(hist, 4, k, wsum, &s_bin, &s_below, tid);
    int T = s_bin;
    int R = (int)(k - s_below);   // rank within bin T (1-indexed)
    __syncthreads();

    // pass 2: collect all (v,n) in bin T, then resolve the R-th smallest locally
    if (tid == 0) s_cnt = 0;
    __syncthreads();
    for (int i = tid; i < m; i += 1024) {
        unsigned v = lv[i];
        if ((int)(v >> 11) == T) {
            int p = atomicAdd(&s_cnt, 1);
            if (p < ECAP) { s_ev[p] = v; s_en[p] = ln[i]; }
        }
    }
    __syncthreads();
    int E = min(s_cnt, ECAP);
    for (int e = tid; e < E; e += 1024) {
        unsigned ve = s_ev[e]; int ne = s_en[e];
        int rk = 0;
        for (int f = 0; f < E; f++) {
            unsigned vf = s_ev[f];
            rk += (vf < ve) || (vf == ve && s_en[f] < ne);
        }
        if (rk == R - 1) { s_V = ve; s_cut = ne; }
    }
    __syncthreads();
    if (tid == 0) { g_thrV[bc] = s_V; g_thrN[bc] = s_cut; }
}

__global__ void __launch_bounds__(256) k_final(const float* __restrict__ gt, float* __restrict__ out) {
    int b = blockIdx.y;
    int j = blockIdx.x * 256 + threadIdx.x;   // a-major
    int a = j / HWn; int r = j - a * HWn; int iy = r >> 6; int ix = r & 63;
    float label = -1.0f;
    float t0 = 0.f, t1 = 0.f, t2 = 0.f, t3 = 0.f;
    unsigned char cls = g_cls[(size_t)b * KAn + j];
    if (cls < 2) {
        int n = g_nidx[j];
        int c = cls ? 0 : 1;
        unsigned v = g_v[(size_t)b * KAn + j];
        unsigned V = g_thrV[b * 2 + c]; int cut = g_thrN[b * 2 + c];
        bool keep = (v < V) || (v == V && n <= cut);
        if (cls == 1) {
            if (keep) {
                label = 1.0f;
                // exact argmax over all 50 gts (first-index tie-break, like jnp.argmax)
                float sx = (float)(ix << 4), sy = (float)(iy << 4);
                float ax1 = c_ax1[a] + sx, ay1 = c_ay1[a] + sy;
                float ax2 = c_ax2[a] + sx, ay2 = c_ay2[a] + sy;
                float areaa = c_area[a];
                const float* gbase = gt + (size_t)b * Gn * 4;
                float best = -1.0f; int arg = 0;
                for (int g = 0; g < Gn; g++) {
                    float gx1 = gbase[g * 4 + 0], gy1 = gbase[g * 4 + 1];
                    float gx2 = gbase[g * 4 + 2], gy2 = gbase[g * 4 + 3];
                    float gw = __fadd_rn(__fsub_rn(gx2, gx1), 1.0f);
                    float gh = __fadd_rn(__fsub_rn(gy2, gy1), 1.0f);
                    float areag = __fmul_rn(gw, gh);
                    float ov = iou_f(ax1, ay1, ax2, ay2, areaa, gx1, gy1, gx2, gy2, areag);
                    if (ov > best) { best = ov; arg = g; }
                }
                const float* gb = gbase + (size_t)arg * 4;
                float gx1 = gb[0], gy1 = gb[1], gx2 = gb[2], gy2 = gb[3];
                float gw = __fadd_rn(__fsub_rn(gx2, gx1), 1.0f);
                float gh = __fadd_rn(__fsub_rn(gy2, gy1), 1.0f);
                float gcx = __fadd_rn(gx1, __fmul_rn(0.5f, __fsub_rn(gw, 1.0f)));
                float gcy = __fadd_rn(gy1, __fmul_rn(0.5f, __fsub_rn(gh, 1.0f)));
                float aw = c_aw[a], ah = c_ah[a];
                float acx = __fadd_rn(ax1, __fmul_rn(0.5f, __fsub_rn(aw, 1.0f)));
                float acy = __fadd_rn(ay1, __fmul_rn(0.5f, __fsub_rn(ah, 1.0f)));
                t0 = __fdiv_rn(__fsub_rn(gcx, acx), aw);
                t1 = __fdiv_rn(__fsub_rn(gcy, acy), ah);
                t2 = logf(__fdiv_rn(gw, aw));
                t3 = logf(__fdiv_rn(gh, ah));
            }
        } else {
            label = keep ? 0.0f : -1.0f;
        }
    }
    out[(size_t)b * An * HWn + (size_t)a * HWn + r] = label;
    float* reg = out + (size_t)Bn * An * HWn;
    size_t rb = (size_t)b * An * 4 * HWn + (size_t)(a * 4) * HWn + r;
    reg[rb] = t0;
    reg[rb + HWn] = t1;
    reg[rb + 2 * HWn] = t2;
    reg[rb + 3 * HWn] = t3;
    // restore scratch state for the next (graph-replayed) run
    g_flags[(size_t)b * KAn + j] = 0u;
    if (blockIdx.x == 0 && threadIdx.x < 2) g_cnt[b * 2 + threadIdx.x] = 0;
}

extern "C" void kernel_launch(void* const* d_in, const int* in_sizes, int n_in,
                              void* d_out, int out_size) {
    (void)in_sizes; (void)n_in; (void)out_size;
    const float* gt = (const float*)d_in[0];
    float* out = (float*)d_out;
    k_gtpass<<<Bn * Gn, 256>>>(gt);
    k_label<<<dim3(KAn / 256, Bn), 256>>>();
    k_select<<<Bn * 2, 1024>>>();
    k_final<<<dim3(KAn / 256, Bn), 256>>>(gt, out);
}

// round 9
// speedup vs baseline: 1.2792x; 1.2792x over previous
#include <cuda_runtime.h>
#include <cstdint>

#define JAX_PARTITIONABLE 1

#define Bn   32
#define Gn   50
#define Hn   64
#define Wn   64
#define An   9
#define HWn  4096
#define KAn  36864
#define HALFN 9312
#define CAP  18624
#define CAPOV 7168
#define ECAP 512

__constant__ int   c_ixmin[9]={6,11,23,4,8,16,3,5,11};
__constant__ int   c_ixmax[9]={57,52,40,59,55,47,60,58,52};
__constant__ int   c_iymin[9]={3,6,12,4,8,16,5,11,22};
__constant__ int   c_iymax[9]={60,57,51,59,55,47,58,52,41};
__constant__ float c_ax1[9]={-84.f,-176.f,-360.f,-56.f,-120.f,-248.f,-36.f,-80.f,-168.f};
__constant__ float c_ay1[9]={-40.f,-88.f,-184.f,-56.f,-120.f,-248.f,-80.f,-168.f,-344.f};
__constant__ float c_ax2[9]={99.f,191.f,375.f,71.f,135.f,263.f,51.f,95.f,183.f};
__constant__ float c_ay2[9]={55.f,103.f,199.f,71.f,135.f,263.f,95.f,183.f,359.f};
__constant__ float c_aw[9] ={184.f,368.f,736.f,128.f,256.f,512.f,88.f,176.f,352.f};
__constant__ float c_ah[9] ={96.f,192.f,384.f,128.f,256.f,512.f,176.f,352.f,704.f};
__constant__ float c_area[9]={17664.f,70656.f,282624.f,16384.f,65536.f,262144.f,15488.f,61952.f,247808.f};

// scratch — zero-initialized at module load; k_final restores that state at the
// end of every run so each kernel_launch (incl. graph replays) is identical.
// g_key64 == 0 is a valid "no positive overlap" state: arg is only consumed for
// fg anchors, which always received at least one positive-ov atomicMax (key>0).
__device__ unsigned           g_keys[Bn][4];
__device__ unsigned long long g_key64[Bn*KAn];   // (ov_bits<<32)|(63-g)
__device__ unsigned char      g_hit[Bn*KAn];
__device__ unsigned char      g_cls[Bn*KAn];     // rewritten fully each run
__device__ unsigned           g_v[Bn*KAn];       // valid where cls<2
__device__ unsigned short     g_nidx[KAn];       // recomputed each run by k_gtpass
__device__ int                g_cnt[Bn*2];
__device__ unsigned           g_lv[Bn*2*CAP];
__device__ int                g_ln[Bn*2*CAP];
__device__ unsigned           g_thrV[Bn*2];      // rewritten each run
__device__ int                g_thrN[Bn*2];

// ---------------- Threefry-2x32 (bit-exact with jax) ----------------
__device__ __forceinline__ void tf2x32(unsigned k0, unsigned k1, unsigned x0, unsigned x1,
                                       unsigned& o0, unsigned& o1) {
    unsigned k2 = k0 ^ k1 ^ 0x1BD11BDAu;
    x0 += k0; x1 += k1;
#define TFR(r) { x0 += x1; x1 = (x1 << (r)) | (x1 >> (32 - (r))); x1 ^= x0; }
    TFR(13) TFR(15) TFR(26) TFR(6)   x0 += k1; x1 += k2 + 1u;
    TFR(17) TFR(29) TFR(16) TFR(24)  x0 += k2; x1 += k0 + 2u;
    TFR(13) TFR(15) TFR(26) TFR(6)   x0 += k0; x1 += k1 + 3u;
    TFR(17) TFR(29) TFR(16) TFR(24)  x0 += k1; x1 += k2 + 4u;
    TFR(13) TFR(15) TFR(26) TFR(6)   x0 += k2; x1 += k0 + 5u;
#undef TFR
    o0 = x0; o1 = x1;
}

__device__ __forceinline__ unsigned ubits(unsigned k0, unsigned k1, int n) {
#if JAX_PARTITIONABLE
    unsigned y0, y1;
    tf2x32(k0, k1, 0u, (unsigned)n, y0, y1);
    return y0 ^ y1;
#else
    unsigned y0, y1;
    if (n < HALFN) { tf2x32(k0, k1, (unsigned)n, (unsigned)(n + HALFN), y0, y1); return y0; }
    else           { tf2x32(k0, k1, (unsigned)(n - HALFN), (unsigned)n, y0, y1); return y1; }
#endif
}

__device__ __forceinline__ int compact_index(int iy, int ix, int a) {
    int n = 0;
#pragma unroll
    for (int j = 0; j < 9; j++) {
        int cy = min(iy, c_iymax[j] + 1) - c_iymin[j]; cy = max(cy, 0);
        int cx = c_ixmax[j] - c_ixmin[j] + 1;
        n += cy * cx;
        if (iy >= c_iymin[j] && iy <= c_iymax[j]) {
            int px = min(ix, c_ixmax[j] + 1) - c_ixmin[j]; px = max(px, 0);
            n += px;
            if (j < a && ix >= c_ixmin[j] && ix <= c_ixmax[j]) n += 1;
        }
    }
    return n;
}

__device__ __forceinline__ float iou_f(float ax1, float ay1, float ax2, float ay2, float areaa,
                                       float gx1, float gy1, float gx2, float gy2, float areag) {
    float iw = __fadd_rn(__fsub_rn(fminf(ax2, gx2), fmaxf(ax1, gx1)), 1.0f); iw = fmaxf(iw, 0.0f);
    float ih = __fadd_rn(__fsub_rn(fminf(ay2, gy2), fmaxf(ay1, gy1)), 1.0f); ih = fmaxf(ih, 0.0f);
    float inter = __fmul_rn(iw, ih);
    return __fdiv_rn(inter, __fsub_rn(__fadd_rn(areaa, areag), inter));
}

// conservative window bounds for anchor type a vs gt box
__device__ __forceinline__ void win(int a, float gx1, float gy1, float gx2, float gy2,
                                    int& xlo, int& xhi, int& ylo, int& yhi) {
    xlo = max(c_ixmin[a], (int)floorf((gx1 - 1.0f - c_ax2[a]) * 0.0625f));
    xhi = min(c_ixmax[a], (int)ceilf((gx2 + 1.0f - c_ax1[a]) * 0.0625f));
    ylo = max(c_iymin[a], (int)floorf((gy1 - 1.0f - c_ay2[a]) * 0.0625f));
    yhi = min(c_iymax[a], (int)ceilf((gy2 + 1.0f - c_ay1[a]) * 0.0625f));
}

// one block per (b,g): pass A computes windowed IoUs (cached in smem), does
// per-anchor 64-bit atomicMax of (ov,63-g), block-reduces this gt's max;
// pass B scans cached IoUs flagging ov==gt_max hits. Blocks <144 also build
// the nidx table; block 0 computes the per-image Threefry keys.
__global__ void __launch_bounds__(256) k_gtpass(const float* __restrict__ gt) {
    __shared__ float sov[CAPOV];
    __shared__ float red[256];
    int blk = blockIdx.x;
    int t = threadIdx.x;
    if (blk < KAn / 256) {
        int i = blk * 256 + t;
        int a = i / HWn; int r = i - a * HWn; int iy = r >> 6; int ix = r & 63;
        g_nidx[i] = (unsigned short)compact_index(iy, ix, a);
    }
    if (blk == 0 && t < Bn) {
        unsigned f0, f1, q0, q1, b0, b1;
        tf2x32(0u, 42u, 0u, (unsigned)t, b0, b1);
        tf2x32(b0, b1, 0u, 0u, f0, f1);
        tf2x32(b0, b1, 0u, 1u, q0, q1);
        g_keys[t][0] = f0; g_keys[t][1] = f1; g_keys[t][2] = q0; g_keys[t][3] = q1;
    }
    int b = blk / Gn, g = blk - b * Gn;
    const float* gb = gt + (size_t)(b * Gn + g) * 4;
    float gx1 = gb[0], gy1 = gb[1], gx2 = gb[2], gy2 = gb[3];
    float gw = __fadd_rn(__fsub_rn(gx2, gx1), 1.0f);
    float gh = __fadd_rn(__fsub_rn(gy2, gy1), 1.0f);
    float areag = __fmul_rn(gw, gh);
    float best = 0.0f;
    unsigned lowbits = (unsigned)(63 - g);

    int xlo9[9], ylo9[9], nx9[9], tot9[9], off9[9];
    int off = 0;
#pragma unroll
    for (int a = 0; a < 9; a++) {
        int xlo, xhi, ylo, yhi;
        win(a, gx1, gy1, gx2, gy2, xlo, xhi, ylo, yhi);
        int nx = xhi - xlo + 1, ny = yhi - ylo + 1;
        int tot = (nx > 0 && ny > 0) ? nx * ny : 0;
        xlo9[a] = xlo; ylo9[a] = ylo; nx9[a] = nx; tot9[a] = tot; off9[a] = off;
        off += tot;
    }
    bool cache = (off <= CAPOV);

#pragma unroll
    for (int a = 0; a < 9; a++) {
        int tot = tot9[a];
        if (tot == 0) continue;
        int xlo = xlo9[a], ylo = ylo9[a], nx = nx9[a], base = off9[a];
        float ax1 = c_ax1[a], ay1 = c_ay1[a], ax2 = c_ax2[a], ay2 = c_ay2[a], areaa = c_area[a];
        for (int q0 = t; q0 < tot; q0 += 256) {
            int q = q0 / nx;
            int iy = ylo + q, ix = xlo + q0 - q * nx;
            float sx = (float)(ix << 4), sy = (float)(iy << 4);
            float ov = iou_f(ax1 + sx, ay1 + sy, ax2 + sx, ay2 + sy, areaa,
                             gx1, gy1, gx2, gy2, areag);
            if (cache) sov[base + q0] = ov;
            if (ov > 0.0f) {
                best = fmaxf(best, ov);
                unsigned long long key = ((unsigned long long)__float_as_uint(ov) << 32) | lowbits;
                atomicMax(&g_key64[(size_t)b * KAn + a * HWn + (iy << 6) + ix], key);
            }
        }
    }
    red[t] = best;
    __syncthreads();
    for (int s = 128; s > 0; s >>= 1) {
        if (t < s) red[t] = fmaxf(red[t], red[t + s]);
        __syncthreads();
    }
    float gm = red[0];
    if (gm <= 0.0f) return;
    // pass B: flag anchors achieving this gt's max overlap
#pragma unroll
    for (int a = 0; a < 9; a++) {
        int tot = tot9[a];
        if (tot == 0) continue;
        int xlo = xlo9[a], ylo = ylo9[a], nx = nx9[a], base = off9[a];
        float ax1 = c_ax1[a], ay1 = c_ay1[a], ax2 = c_ax2[a], ay2 = c_ay2[a], areaa = c_area[a];
        for (int q0 = t; q0 < tot; q0 += 256) {
            int q = q0 / nx;
            int iy = ylo + q, ix = xlo + q0 - q * nx;
            float ov;
            if (cache) {
                ov = sov[base + q0];
            } else {
                float sx = (float)(ix << 4), sy = (float)(iy << 4);
                ov = iou_f(ax1 + sx, ay1 + sy, ax2 + sx, ay2 + sy, areaa,
                           gx1, gy1, gx2, gy2, areag);
            }
            if (ov == gm) g_hit[(size_t)b * KAn + a * HWn + (iy << 6) + ix] = 1;
        }
    }
}

__global__ void __launch_bounds__(256) k_label() {
    __shared__ int lcnt[2];
    __shared__ int lbase[2];
    int b = blockIdx.y;
    int t = threadIdx.x;
    if (t < 2) lcnt[t] = 0;
    __syncthreads();
    int j = blockIdx.x * 256 + t;       // a-major
    int a = j / HWn; int r = j - a * HWn; int iy = r >> 6; int ix = r & 63;
    unsigned char cls = 3;
    int c = 0, lp = 0, n = 0; unsigned v = 0;
    if (!(ix < c_ixmin[a] || ix > c_ixmax[a] || iy < c_iymin[a] || iy > c_iymax[a])) {
        unsigned long long key = g_key64[(size_t)b * KAn + j];
        float best = __uint_as_float((unsigned)(key >> 32));
        bool hit = g_hit[(size_t)b * KAn + j] != 0;
        cls = (hit || best >= 0.7f) ? (unsigned char)1
            : ((best < 0.3f) ? (unsigned char)0 : (unsigned char)2);
        if (cls < 2) {
            c = cls ? 0 : 1;
            n = g_nidx[j];
            v = ubits(g_keys[b][c * 2], g_keys[b][c * 2 + 1], n) >> 9;
            g_v[(size_t)b * KAn + j] = v;
            lp = atomicAdd(&lcnt[c], 1);
        }
    }
    g_cls[(size_t)b * KAn + j] = cls;
    __syncthreads();
    if (t < 2) lbase[t] = lcnt[t] ? atomicAdd(&g_cnt[b * 2 + t], lcnt[t]) : 0;
    __syncthreads();
    if (cls < 2) {
        int p = (b * 2 + c) * CAP + lbase[c] + lp;
        g_lv[p] = v;
        g_ln[p] = n;
    }
}

__device__ void find_kth(unsigned* hist, int per, unsigned k, unsigned* wsum,
                         int* s_bin, unsigned* s_below, int tid) {
    int base = tid * per;
    unsigned mysum = 0;
    for (int x = 0; x < per; x++) mysum += hist[base + x];
    unsigned lane = tid & 31, wid = tid >> 5;
    unsigned inc = mysum;
#pragma unroll
    for (int off = 1; off < 32; off <<= 1) {
        unsigned nv = __shfl_up_sync(0xffffffffu, inc, off);
        if (lane >= off) inc += nv;
    }
    if (lane == 31) wsum[wid] = inc;
    __syncthreads();
    if (wid == 0) {
        unsigned w = wsum[lane];
        unsigned iw = w;
#pragma unroll
        for (int off = 1; off < 32; off <<= 1) {
            unsigned nv = __shfl_up_sync(0xffffffffu, iw, off);
            if (lane >= off) iw += nv;
        }
        wsum[lane] = iw - w;
    }
    __syncthreads();
    unsigned run = wsum[wid] + (inc - mysum);
    for (int x = 0; x < per; x++) {
        unsigned h = hist[base + x];
        if (run < k && k <= run + h) { *s_bin = base + x; *s_below = run; }
        run += h;
    }
    __syncthreads();
}

__global__ void __launch_bounds__(1024) k_select() {
    __shared__ unsigned hist[4096];
    __shared__ unsigned wsum[32];
    __shared__ int s_bin; __shared__ unsigned s_below;
    __shared__ unsigned s_ev[ECAP]; __shared__ int s_en[ECAP];
    __shared__ int s_cnt; __shared__ unsigned s_V; __shared__ int s_cut;
    int bc = blockIdx.x; int b = bc >> 1; int c = bc & 1;
    int tid = threadIdx.x;
    int nfg = g_cnt[b * 2 + 0], nbg = g_cnt[b * 2 + 1];
    int m = c ? nbg : nfg;
    unsigned k = c ? (unsigned)(256 - min(nfg, 128)) : 128u;
    if ((unsigned)m <= k) {
        if (tid == 0) { g_thrV[bc] = 0xFFFFFFFFu; g_thrN[bc] = 0x7FFFFFFF; }
        return;
    }
    const unsigned* lv = g_lv + (size_t)bc * CAP;
    const int* ln = g_ln + (size_t)bc * CAP;

    // pass 1: 12-bit histogram
    for (int x = tid; x < 4096; x += 1024) hist[x] = 0;
    __syncthreads();
    for (int i = tid; i < m; i += 1024) atomicAdd(&hist[lv[i] >> 11], 1u);
    __syncthreads();
    find_kth(hist, 4, k, wsum, &s_bin, &s_below, tid);
    int T = s_bin;
    int R = (int)(k - s_below);   // rank within bin T (1-indexed)
    __syncthreads();

    // pass 2: collect all (v,n) in bin T, resolve the R-th smallest locally
    if (tid == 0) s_cnt = 0;
    __syncthreads();
    for (int i = tid; i < m; i += 1024) {
        unsigned v = lv[i];
        if ((int)(v >> 11) == T) {
            int p = atomicAdd(&s_cnt, 1);
            if (p < ECAP) { s_ev[p] = v; s_en[p] = ln[i]; }
        }
    }
    __syncthreads();
    int E = min(s_cnt, ECAP);
    for (int e = tid; e < E; e += 1024) {
        unsigned ve = s_ev[e]; int ne = s_en[e];
        int rk = 0;
        for (int f = 0; f < E; f++) {
            unsigned vf = s_ev[f];
            rk += (vf < ve) || (vf == ve && s_en[f] < ne);
        }
        if (rk == R - 1) { s_V = ve; s_cut = ne; }
    }
    __syncthreads();
    if (tid == 0) { g_thrV[bc] = s_V; g_thrN[bc] = s_cut; }
}

__global__ void __launch_bounds__(256) k_final(const float* __restrict__ gt, float* __restrict__ out) {
    int b = blockIdx.y;
    int j = blockIdx.x * 256 + threadIdx.x;   // a-major
    int a = j / HWn; int r = j - a * HWn; int iy = r >> 6; int ix = r & 63;
    float label = -1.0f;
    float t0 = 0.f, t1 = 0.f, t2 = 0.f, t3 = 0.f;
    unsigned char cls = g_cls[(size_t)b * KAn + j];
    if (cls < 2) {
        int n = g_nidx[j];
        int c = cls ? 0 : 1;
        unsigned v = g_v[(size_t)b * KAn + j];
        unsigned V = g_thrV[b * 2 + c]; int cut = g_thrN[b * 2 + c];
        bool keep = (v < V) || (v == V && n <= cut);
        if (cls == 1) {
            if (keep) {
                label = 1.0f;
                unsigned long long key = g_key64[(size_t)b * KAn + j];
                int arg = 63 - (int)(key & 0xFFFFFFFFu);
                const float* gb = gt + (size_t)(b * Gn + arg) * 4;
                float gx1 = gb[0], gy1 = gb[1], gx2 = gb[2], gy2 = gb[3];
                float gw = __fadd_rn(__fsub_rn(gx2, gx1), 1.0f);
                float gh = __fadd_rn(__fsub_rn(gy2, gy1), 1.0f);
                float gcx = __fadd_rn(gx1, __fmul_rn(0.5f, __fsub_rn(gw, 1.0f)));
                float gcy = __fadd_rn(gy1, __fmul_rn(0.5f, __fsub_rn(gh, 1.0f)));
                float sx = (float)(ix << 4), sy = (float)(iy << 4);
                float aw = c_aw[a], ah = c_ah[a];
                float acx = __fadd_rn(__fadd_rn(c_ax1[a], sx), __fmul_rn(0.5f, __fsub_rn(aw, 1.0f)));
                float acy = __fadd_rn(__fadd_rn(c_ay1[a], sy), __fmul_rn(0.5f, __fsub_rn(ah, 1.0f)));
                t0 = __fdiv_rn(__fsub_rn(gcx, acx), aw);
                t1 = __fdiv_rn(__fsub_rn(gcy, acy), ah);
                t2 = logf(__fdiv_rn(gw, aw));
                t3 = logf(__fdiv_rn(gh, ah));
            }
        } else {
            label = keep ? 0.0f : -1.0f;
        }
    }
    out[(size_t)b * An * HWn + (size_t)a * HWn + r] = label;
    float* reg = out + (size_t)Bn * An * HWn;
    size_t rb = (size_t)b * An * 4 * HWn + (size_t)(a * 4) * HWn + r;
    reg[rb] = t0;
    reg[rb + HWn] = t1;
    reg[rb + 2 * HWn] = t2;
    reg[rb + 3 * HWn] = t3;
    // restore load-time scratch state for the next (graph-replayed) run
    g_key64[(size_t)b * KAn + j] = 0ull;
    g_hit[(size_t)b * KAn + j] = 0;
    if (blockIdx.x == 0 && threadIdx.x < 2) g_cnt[b * 2 + threadIdx.x] = 0;
}

extern "C" void kernel_launch(void* const* d_in, const int* in_sizes, int n_in,
                              void* d_out, int out_size) {
    (void)in_sizes; (void)n_in; (void)out_size;
    const float* gt = (const float*)d_in[0];
    float* out = (float*)d_out;
    k_gtpass<<<Bn * Gn, 256>>>(gt);
    k_label<<<dim3(KAn / 256, Bn), 256>>>();
    k_select<<<Bn * 2, 1024>>>();
    k_final<<<dim3(KAn / 256, Bn), 256>>>(gt, out);
}